// round 9
// baseline (speedup 1.0000x reference)
#include <cuda_runtime.h>

#define SEQ 512
#define HIDDEN 512
#define HD 64
#define NPART 8

// ---------------------------------------------------------------------------
// Scratch (static __device__, no allocation)
// ---------------------------------------------------------------------------
__device__ unsigned g_Xh[SEQ * 256], g_Xl[SEQ * 256];
__device__ unsigned g_Wqh[SEQ * 256], g_Wql[SEQ * 256];
__device__ unsigned g_Wkh[SEQ * 256], g_Wkl[SEQ * 256];
__device__ unsigned g_Wvh[SEQ * 256], g_Wvl[SEQ * 256];
__device__ unsigned g_Woh[SEQ * 256], g_Wol[SEQ * 256];
__device__ float    g_q[SEQ * HIDDEN], g_k[SEQ * HIDDEN], g_v[SEQ * HIDDEN];
__device__ unsigned g_qh[SEQ * 256], g_ql[SEQ * 256];
__device__ unsigned g_kh[SEQ * 256], g_kl[SEQ * 256];
__device__ float    g_zq[8 * SEQ], g_zkm[8 * SEQ];
__device__ float    g_ctx[NPART][SEQ * HIDDEN];

// ---------------------------------------------------------------------------
// bf16x3 split + mma + cp.async + packed f32x2 helpers
// ---------------------------------------------------------------------------
__device__ __forceinline__ void split2(float x0, float x1, unsigned& hi, unsigned& lo)
{
    unsigned u0 = __float_as_uint(x0), u1 = __float_as_uint(x1);
    unsigned h;
    asm("prmt.b32 %0, %1, %2, 0x7632;" : "=r"(h) : "r"(u0), "r"(u1));
    float l0 = x0 - __uint_as_float(u0 & 0xFFFF0000u);
    float l1 = x1 - __uint_as_float(u1 & 0xFFFF0000u);
    unsigned lp;
    asm("cvt.rn.bf16x2.f32 %0, %1, %2;" : "=r"(lp) : "f"(l1), "f"(l0));
    hi = h; lo = lp;
}

__device__ __forceinline__ void mma_bf16(float* c,
    unsigned a0, unsigned a1, unsigned a2, unsigned a3, unsigned b0, unsigned b1)
{
    asm("mma.sync.aligned.m16n8k16.row.col.f32.bf16.bf16.f32 "
        "{%0,%1,%2,%3}, {%4,%5,%6,%7}, {%8,%9}, {%0,%1,%2,%3};"
        : "+f"(c[0]), "+f"(c[1]), "+f"(c[2]), "+f"(c[3])
        : "r"(a0), "r"(a1), "r"(a2), "r"(a3), "r"(b0), "r"(b1));
}

__device__ __forceinline__ void cp16(void* dst, const void* src)
{
    unsigned d = (unsigned)__cvta_generic_to_shared(dst);
    asm volatile("cp.async.cg.shared.global [%0], [%1], 16;" :: "r"(d), "l"(src));
}
#define CP_COMMIT() asm volatile("cp.async.commit_group;")

__device__ __forceinline__ void fma2_acc(unsigned long long& acc, float a, float b,
                                         unsigned long long one2)
{
    asm("{\n\t.reg .b64 p;\n\tmov.b64 p, {%1,%2};\n\tfma.rn.f32x2 %0, p, %3, %0;\n\t}"
        : "+l"(acc) : "f"(a), "f"(b), "l"(one2));
}
__device__ __forceinline__ void add2_acc(unsigned long long& acc, float a, float b)
{
    asm("{\n\t.reg .b64 p;\n\tmov.b64 p, {%1,%2};\n\tadd.rn.f32x2 %0, %0, p;\n\t}"
        : "+l"(acc) : "f"(a), "f"(b));
}
__device__ __forceinline__ void unpack2(unsigned long long v, float& lo, float& hi)
{
    asm("mov.b64 {%0,%1}, %2;" : "=f"(lo), "=f"(hi) : "l"(v));
}

// ---------------------------------------------------------------------------
// Convert: split 5 f32 matrices into packed hi/lo planes. grid (512,1,5)x256.
// ---------------------------------------------------------------------------
__global__ __launch_bounds__(256) void convert_kernel(
    const float* __restrict__ X, const float* __restrict__ Wq,
    const float* __restrict__ Wk, const float* __restrict__ Wv,
    const float* __restrict__ Wo)
{
    const float* src; unsigned* dh; unsigned* dl;
    switch (blockIdx.z) {
        case 0:  src = X;  dh = g_Xh;  dl = g_Xl;  break;
        case 1:  src = Wq; dh = g_Wqh; dl = g_Wql; break;
        case 2:  src = Wk; dh = g_Wkh; dl = g_Wkl; break;
        case 3:  src = Wv; dh = g_Wvh; dl = g_Wvl; break;
        default: src = Wo; dh = g_Woh; dl = g_Wol; break;
    }
    int idx = blockIdx.x * 256 + threadIdx.x;
    float2 v = *(const float2*)(src + idx * 2);
    unsigned h, l; split2(v.x, v.y, h, l);
    dh[idx] = h; dl[idx] = l;
}

// ---------------------------------------------------------------------------
// GEMM NT on pre-split planes (32x64 tile, cp.async 4-stage), as R6-R8.
// ---------------------------------------------------------------------------
__device__ __forceinline__ void gemm_planes(
    const unsigned* __restrict__ Aph, const unsigned* __restrict__ Apl,
    const unsigned* __restrict__ Bph, const unsigned* __restrict__ Bpl,
    const float* __restrict__ bias, float* __restrict__ out,
    unsigned* __restrict__ outh, unsigned* __restrict__ outl)
{
    __shared__ unsigned smA[4][2][32][12];
    __shared__ unsigned smB[4][2][64][12];

    int t = threadIdx.x;
    int row0 = blockIdx.y * 32, col0 = blockIdx.x * 64;
    int lane = t & 31, warp = t >> 5;
    int wm = warp >> 1, wn = warp & 1;
    int g = lane >> 2, tq = lane & 3;

    int p = t >> 6;
    int ar = (t >> 1) & 31, ahalf = t & 1;
    int br = t & 63;

    const unsigned* Asrc = (p ? Apl : Aph) + (row0 + ar) * 256 + ahalf * 4;
    const unsigned* Bsrc = (p ? Bpl : Bph) + (col0 + br) * 256;

    float acc[4][4];
#pragma unroll
    for (int nt = 0; nt < 4; nt++)
#pragma unroll
        for (int x = 0; x < 4; x++) acc[nt][x] = 0.0f;

#pragma unroll
    for (int s = 0; s < 3; s++) {
        cp16(&smA[s][p][ar][ahalf * 4], Asrc + s * 8);
        cp16(&smB[s][p][br][0], Bsrc + s * 8);
        cp16(&smB[s][p][br][4], Bsrc + s * 8 + 4);
        CP_COMMIT();
    }

#pragma unroll 1
    for (int kb = 0; kb < 32; kb++) {
        asm volatile("cp.async.wait_group 2;");
        __syncthreads();
        if (kb + 3 < 32) {
            int s = (kb + 3) & 3;
            cp16(&smA[s][p][ar][ahalf * 4], Asrc + (kb + 3) * 8);
            cp16(&smB[s][p][br][0], Bsrc + (kb + 3) * 8);
            cp16(&smB[s][p][br][4], Bsrc + (kb + 3) * 8 + 4);
        }
        CP_COMMIT();

        int st = kb & 3;
        int r = wm * 16 + g;
        unsigned ah0 = smA[st][0][r][tq],     ah1 = smA[st][0][r + 8][tq];
        unsigned ah2 = smA[st][0][r][tq + 4], ah3 = smA[st][0][r + 8][tq + 4];
        unsigned al0 = smA[st][1][r][tq],     al1 = smA[st][1][r + 8][tq];
        unsigned al2 = smA[st][1][r][tq + 4], al3 = smA[st][1][r + 8][tq + 4];
#pragma unroll
        for (int nt = 0; nt < 4; nt++) {
            int n = wn * 32 + nt * 8 + g;
            unsigned bh0 = smB[st][0][n][tq], bh1 = smB[st][0][n][tq + 4];
            unsigned bl0 = smB[st][1][n][tq], bl1 = smB[st][1][n][tq + 4];
            mma_bf16(acc[nt], ah0, ah1, ah2, ah3, bh0, bh1);
            mma_bf16(acc[nt], ah0, ah1, ah2, ah3, bl0, bl1);
            mma_bf16(acc[nt], al0, al1, al2, al3, bh0, bh1);
        }
    }
    asm volatile("cp.async.wait_group 0;");

#pragma unroll
    for (int nt = 0; nt < 4; nt++) {
        int row = row0 + wm * 16 + g;
        int col = col0 + wn * 32 + nt * 8 + 2 * tq;
        float2 b2 = *(const float2*)(bias + col);
        float v0 = acc[nt][0] + b2.x, v1 = acc[nt][1] + b2.y;
        float v2 = acc[nt][2] + b2.x, v3 = acc[nt][3] + b2.y;
        *(float2*)(out + row * HIDDEN + col) = make_float2(v0, v1);
        *(float2*)(out + (row + 8) * HIDDEN + col) = make_float2(v2, v3);
        if (outh) {
            unsigned h, l;
            split2(v0, v1, h, l);
            outh[row * 256 + (col >> 1)] = h; outl[row * 256 + (col >> 1)] = l;
            split2(v2, v3, h, l);
            outh[(row + 8) * 256 + (col >> 1)] = h; outl[(row + 8) * 256 + (col >> 1)] = l;
        }
    }
}

__global__ __launch_bounds__(128) void qkv_mma_kernel(
    const float* __restrict__ bq, const float* __restrict__ bk,
    const float* __restrict__ bv)
{
    if (blockIdx.z == 0)
        gemm_planes(g_Xh, g_Xl, g_Wqh, g_Wql, bq, g_q, g_qh, g_ql);
    else if (blockIdx.z == 1)
        gemm_planes(g_Xh, g_Xl, g_Wkh, g_Wkl, bk, g_k, g_kh, g_kl);
    else
        gemm_planes(g_Xh, g_Xl, g_Wvh, g_Wvl, bv, g_v, (unsigned*)0, (unsigned*)0);
}

// ---------------------------------------------------------------------------
// Output GEMM with FUSED 8-partial reduction in the A-loader:
// A[i][h] = sum_p ctx[p][i][h], summed + bf16x3-split on the fly (register
// prefetch, one stage ahead). B (Wo planes) keeps the cp.async pipeline.
// ---------------------------------------------------------------------------
__global__ __launch_bounds__(128) void out_mma_kernel(
    const float* __restrict__ bo, float* __restrict__ out)
{
    __shared__ unsigned smA[4][2][32][12];
    __shared__ unsigned smB[4][2][64][12];

    int t = threadIdx.x;
    int row0 = blockIdx.y * 32, col0 = blockIdx.x * 64;
    int lane = t & 31, warp = t >> 5;
    int wm = warp >> 1, wn = warp & 1;
    int g = lane >> 2, tq = lane & 3;

    int ar2 = t >> 2, aseg = t & 3;        // A: row (0..31), float4 segment
    int p = t >> 6, br = t & 63;           // B: plane, row

    const unsigned* Bsrc = (p ? g_Wol : g_Woh) + (col0 + br) * 256;
    int aoff = (row0 + ar2) * HIDDEN + aseg * 4;

    float acc[4][4];
#pragma unroll
    for (int nt = 0; nt < 4; nt++)
#pragma unroll
        for (int x = 0; x < 4; x++) acc[nt][x] = 0.0f;

    // stage 0..2: direct load+sum+split+STS for A; cp.async for B
#pragma unroll
    for (int s = 0; s < 3; s++) {
        float4 sum = make_float4(0.0f, 0.0f, 0.0f, 0.0f);
#pragma unroll
        for (int pp = 0; pp < NPART; pp++) {
            float4 v = *(const float4*)&g_ctx[pp][aoff + s * 16];
            sum.x += v.x; sum.y += v.y; sum.z += v.z; sum.w += v.w;
        }
        unsigned h0, l0, h1, l1;
        split2(sum.x, sum.y, h0, l0); split2(sum.z, sum.w, h1, l1);
        *(uint2*)&smA[s][0][ar2][aseg * 2] = make_uint2(h0, h1);
        *(uint2*)&smA[s][1][ar2][aseg * 2] = make_uint2(l0, l1);
        cp16(&smB[s][p][br][0], Bsrc + s * 8);
        cp16(&smB[s][p][br][4], Bsrc + s * 8 + 4);
        CP_COMMIT();
    }

    // prefetch A raw partials for stage 3
    float4 aP[NPART];
#pragma unroll
    for (int pp = 0; pp < NPART; pp++)
        aP[pp] = *(const float4*)&g_ctx[pp][aoff + 3 * 16];

#pragma unroll 1
    for (int kb = 0; kb < 32; kb++) {
        asm volatile("cp.async.wait_group 2;");
        __syncthreads();
        if (kb + 3 < 32) {
            int s = (kb + 3) & 3;
            float4 sum = make_float4(0.0f, 0.0f, 0.0f, 0.0f);
#pragma unroll
            for (int pp = 0; pp < NPART; pp++) {
                sum.x += aP[pp].x; sum.y += aP[pp].y;
                sum.z += aP[pp].z; sum.w += aP[pp].w;
            }
            unsigned h0, l0, h1, l1;
            split2(sum.x, sum.y, h0, l0); split2(sum.z, sum.w, h1, l1);
            *(uint2*)&smA[s][0][ar2][aseg * 2] = make_uint2(h0, h1);
            *(uint2*)&smA[s][1][ar2][aseg * 2] = make_uint2(l0, l1);
            if (kb + 4 < 32) {
#pragma unroll
                for (int pp = 0; pp < NPART; pp++)
                    aP[pp] = *(const float4*)&g_ctx[pp][aoff + (kb + 4) * 16];
            }
            cp16(&smB[s][p][br][0], Bsrc + (kb + 3) * 8);
            cp16(&smB[s][p][br][4], Bsrc + (kb + 3) * 8 + 4);
        }
        CP_COMMIT();

        int st = kb & 3;
        int r = wm * 16 + g;
        unsigned ah0 = smA[st][0][r][tq],     ah1 = smA[st][0][r + 8][tq];
        unsigned ah2 = smA[st][0][r][tq + 4], ah3 = smA[st][0][r + 8][tq + 4];
        unsigned al0 = smA[st][1][r][tq],     al1 = smA[st][1][r + 8][tq];
        unsigned al2 = smA[st][1][r][tq + 4], al3 = smA[st][1][r + 8][tq + 4];
#pragma unroll
        for (int nt = 0; nt < 4; nt++) {
            int n = wn * 32 + nt * 8 + g;
            unsigned bh0 = smB[st][0][n][tq], bh1 = smB[st][0][n][tq + 4];
            unsigned bl0 = smB[st][1][n][tq], bl1 = smB[st][1][n][tq + 4];
            mma_bf16(acc[nt], ah0, ah1, ah2, ah3, bh0, bh1);
            mma_bf16(acc[nt], ah0, ah1, ah2, ah3, bl0, bl1);
            mma_bf16(acc[nt], al0, al1, al2, al3, bh0, bh1);
        }
    }
    asm volatile("cp.async.wait_group 0;");

#pragma unroll
    for (int nt = 0; nt < 4; nt++) {
        int row = row0 + wm * 16 + g;
        int col = col0 + wn * 32 + nt * 8 + 2 * tq;
        float2 b2 = *(const float2*)(bo + col);
        *(float2*)(out + row * HIDDEN + col) =
            make_float2(acc[nt][0] + b2.x, acc[nt][1] + b2.y);
        *(float2*)(out + (row + 8) * HIDDEN + col) =
            make_float2(acc[nt][2] + b2.x, acc[nt][3] + b2.y);
    }
}

// ---------------------------------------------------------------------------
// Norms: zq[h][i] = coef*|q|^2 ; zkm[h][j] = coef*|k|^2 + zc + (1-mask)*1e10
// ---------------------------------------------------------------------------
__global__ __launch_bounds__(128) void norm_kernel(
    const float* __restrict__ mask, const float* __restrict__ gamma)
{
    int id = blockIdx.x * 128 + threadIdx.x;
    int which = id >> 12, head = (id >> 9) & 7, row = id & 511;
    const float* src = (which ? g_k : g_q) + row * HIDDEN + head * HD;
    float s = 0.0f;
#pragma unroll
    for (int c = 0; c < 16; c++) {
        float4 f = *(const float4*)(src + c * 4);
        s = fmaf(f.x, f.x, s); s = fmaf(f.y, f.y, s);
        s = fmaf(f.z, f.z, s); s = fmaf(f.w, f.w, s);
    }
    float gsd = gamma[0] * 8.0f;
    float coef = 15.0f / (16.0f * gsd);
    float zc = 12.0f / gsd;
    if (which)
        g_zkm[head * SEQ + row] = fmaf(coef, s, zc + (1.0f - mask[row]) * 1e10f);
    else
        g_zq[head * SEQ + row] = coef * s;
}

// ---------------------------------------------------------------------------
// FUSED inhibitor: CTA = (i-tile 64, head, j-part 64), 256 threads (8 warps).
// Per 32-j chunk: MMA z-tile (bf16x3) -> affine epilogue -> zst transposed
// smem -> streaming accumulation (4i x 4k per thread, packed f32x2).
// ctx[i,k] = sum_j max(v,z) - sum_j z.
// ---------------------------------------------------------------------------
__global__ __launch_bounds__(256) void fused_kernel(const float* __restrict__ gamma)
{
    __shared__ unsigned smq[2][64][36];  // q hi/lo planes [row][packed-k]
    __shared__ unsigned smk[2][32][36];  // k chunk planes
    __shared__ float vs[32][68];         // v chunk [j][k]
    __shared__ float zst[32][68];        // z tile TRANSPOSED [j][i]

    int t = threadIdx.x;
    int i0 = blockIdx.x * 64, head = blockIdx.y, jp = blockIdx.z;
    int j0 = jp * 64;

    // stage q planes (cp.async)
    {
        int p = t >> 7, row = (t >> 1) & 63, half = t & 1;
        const unsigned* src = (p ? g_ql : g_qh) + (i0 + row) * 256 + head * 32 + half * 16;
#pragma unroll
        for (int s = 0; s < 4; s++)
            cp16(&smq[p][row][half * 16 + s * 4], src + s * 4);
        CP_COMMIT();
    }

    // prefetch chunk 0: k planes + v (registers)
    int kp = t >> 7, krow = (t >> 2) & 31, kq4 = t & 3;
    const unsigned* kplane = kp ? g_kl : g_kh;
    uint4 kr0, kr1;
    {
        const unsigned* s0 = kplane + (j0 + krow) * 256 + head * 32 + kq4 * 8;
        kr0 = *(const uint4*)(s0); kr1 = *(const uint4*)(s0 + 4);
    }
    int vrow = t >> 3, vseg = t & 7;
    float4 vr0, vr1;
    {
        const float* s0 = g_v + (j0 + vrow) * HIDDEN + head * HD + vseg * 8;
        vr0 = *(const float4*)(s0); vr1 = *(const float4*)(s0 + 4);
    }

    int lane = t & 31, warp = t >> 5;
    int wm = warp >> 1, wn = warp & 1;
    int g = lane >> 2, tq = lane & 3;

    float gsd = gamma[0] * 8.0f;
    float m2c = -2.0f * 15.0f / (16.0f * gsd);
    float zq0 = g_zq[head * SEQ + i0 + wm * 16 + g];
    float zq1 = g_zq[head * SEQ + i0 + wm * 16 + g + 8];

    int ig = t >> 4, kg = t & 15;   // accumulation: 4i x 4k per thread

    const unsigned long long one2 = 0x3F8000003F800000ULL;
    unsigned long long acc2[4][2];
#pragma unroll
    for (int a = 0; a < 4; a++) { acc2[a][0] = 0ULL; acc2[a][1] = 0ULL; }
    unsigned long long accz01 = 0ULL, accz23 = 0ULL;

    asm volatile("cp.async.wait_group 0;");

#pragma unroll 1
    for (int c = 0; c < 2; c++) {
        __syncthreads();   // prev chunk consumers done; q visible (c=0)
        *(uint4*)&smk[kp][krow][kq4 * 8]     = kr0;
        *(uint4*)&smk[kp][krow][kq4 * 8 + 4] = kr1;
        *(float4*)&vs[vrow][vseg * 8]     = vr0;
        *(float4*)&vs[vrow][vseg * 8 + 4] = vr1;
        if (c < 1) {
            const unsigned* s0 = kplane + (j0 + 32 + krow) * 256 + head * 32 + kq4 * 8;
            kr0 = *(const uint4*)(s0); kr1 = *(const uint4*)(s0 + 4);
            const float* sv = g_v + (j0 + 32 + vrow) * HIDDEN + head * HD + vseg * 8;
            vr0 = *(const float4*)(sv); vr1 = *(const float4*)(sv + 4);
        }
        __syncthreads();

        // z = m2c*(q.k) + zq[i] + zkm[j] via mma, into zst (transposed)
        {
            float za[2][4];
#pragma unroll
            for (int nt = 0; nt < 2; nt++)
#pragma unroll
                for (int x = 0; x < 4; x++) za[nt][x] = 0.0f;

            int r = wm * 16 + g;
#pragma unroll
            for (int kb = 0; kb < 4; kb++) {
                int base = kb * 8;
                unsigned ah0 = smq[0][r][base + tq],     ah1 = smq[0][r + 8][base + tq];
                unsigned ah2 = smq[0][r][base + tq + 4], ah3 = smq[0][r + 8][base + tq + 4];
                unsigned al0 = smq[1][r][base + tq],     al1 = smq[1][r + 8][base + tq];
                unsigned al2 = smq[1][r][base + tq + 4], al3 = smq[1][r + 8][base + tq + 4];
#pragma unroll
                for (int nt = 0; nt < 2; nt++) {
                    int n = wn * 16 + nt * 8 + g;
                    unsigned bh0 = smk[0][n][base + tq], bh1 = smk[0][n][base + tq + 4];
                    unsigned bl0 = smk[1][n][base + tq], bl1 = smk[1][n][base + tq + 4];
                    mma_bf16(za[nt], ah0, ah1, ah2, ah3, bh0, bh1);
                    mma_bf16(za[nt], ah0, ah1, ah2, ah3, bl0, bl1);
                    mma_bf16(za[nt], al0, al1, al2, al3, bh0, bh1);
                }
            }
#pragma unroll
            for (int nt = 0; nt < 2; nt++) {
                int col = wn * 16 + nt * 8 + 2 * tq;
                float2 zk = *(const float2*)(g_zkm + head * SEQ + j0 + c * 32 + col);
                zst[col][r]         = fmaf(m2c, za[nt][0], zq0 + zk.x);
                zst[col + 1][r]     = fmaf(m2c, za[nt][1], zq0 + zk.y);
                zst[col][r + 8]     = fmaf(m2c, za[nt][2], zq1 + zk.x);
                zst[col + 1][r + 8] = fmaf(m2c, za[nt][3], zq1 + zk.y);
            }
        }
        __syncthreads();

        // accumulation: acc2 += max(v, z) (packed); accz += z (packed)
#pragma unroll 4
        for (int jj = 0; jj < 32; jj++) {
            float4 z4 = *(const float4*)&zst[jj][ig * 4];
            float4 v4 = *(const float4*)&vs[jj][kg * 4];
            add2_acc(accz01, z4.x, z4.y);
            add2_acc(accz23, z4.z, z4.w);
            float za[4] = {z4.x, z4.y, z4.z, z4.w};
#pragma unroll
            for (int a = 0; a < 4; a++) {
                float z = za[a];
                fma2_acc(acc2[a][0], fmaxf(v4.x, z), fmaxf(v4.y, z), one2);
                fma2_acc(acc2[a][1], fmaxf(v4.z, z), fmaxf(v4.w, z), one2);
            }
        }
    }

    float az[4];
    unpack2(accz01, az[0], az[1]);
    unpack2(accz23, az[2], az[3]);
#pragma unroll
    for (int a = 0; a < 4; a++) {
        float a0, a1, a2, a3;
        unpack2(acc2[a][0], a0, a1);
        unpack2(acc2[a][1], a2, a3);
        float* outp = g_ctx[jp] + (i0 + ig * 4 + a) * HIDDEN + head * HD + kg * 4;
        *(float4*)outp = make_float4(a0 - az[a], a1 - az[a], a2 - az[a], a3 - az[a]);
    }
}

extern "C" void kernel_launch(void* const* d_in, const int* in_sizes, int n_in,
                              void* d_out, int out_size)
{
    const float* X     = (const float*)d_in[0];
    const float* mask  = (const float*)d_in[1];
    const float* Wq    = (const float*)d_in[2];
    const float* bq    = (const float*)d_in[3];
    const float* Wk    = (const float*)d_in[4];
    const float* bk    = (const float*)d_in[5];
    const float* Wv    = (const float*)d_in[6];
    const float* bv    = (const float*)d_in[7];
    const float* Wo    = (const float*)d_in[8];
    const float* bo    = (const float*)d_in[9];
    const float* gamma = (const float*)d_in[10];
    float* out = (float*)d_out;

    convert_kernel<<<dim3(512, 1, 5), 256>>>(X, Wq, Wk, Wv, Wo);
    qkv_mma_kernel<<<dim3(8, 16, 3), 128>>>(bq, bk, bv);
    norm_kernel<<<64, 128>>>(mask, gamma);
    fused_kernel<<<dim3(8, 8, NPART), 256>>>(gamma);
    out_mma_kernel<<<dim3(8, 16), 128>>>(bo, out);
}

// round 10
// speedup vs baseline: 1.1240x; 1.1240x over previous
#include <cuda_runtime.h>

#define SEQ 512
#define HIDDEN 512
#define HD 64
#define NPART 8

// ---------------------------------------------------------------------------
// Scratch (static __device__, no allocation)
// ---------------------------------------------------------------------------
__device__ unsigned g_Xh[SEQ * 256], g_Xl[SEQ * 256];
__device__ unsigned g_Wqh[SEQ * 256], g_Wql[SEQ * 256];
__device__ unsigned g_Wkh[SEQ * 256], g_Wkl[SEQ * 256];
__device__ unsigned g_Wvh[SEQ * 256], g_Wvl[SEQ * 256];
__device__ unsigned g_Woh[SEQ * 256], g_Wol[SEQ * 256];
__device__ float    g_q[SEQ * HIDDEN], g_k[SEQ * HIDDEN], g_v[SEQ * HIDDEN];
__device__ unsigned g_qh[SEQ * 256], g_ql[SEQ * 256];
__device__ unsigned g_kh[SEQ * 256], g_kl[SEQ * 256];
__device__ float    g_zq[8 * SEQ], g_zkm[8 * SEQ];
__device__ float    g_ctx[NPART][SEQ * HIDDEN];
__device__ unsigned g_Ch[SEQ * 256], g_Cl[SEQ * 256];

// ---------------------------------------------------------------------------
// bf16x3 split + mma + cp.async + packed f32x2 helpers
// ---------------------------------------------------------------------------
__device__ __forceinline__ void split2(float x0, float x1, unsigned& hi, unsigned& lo)
{
    unsigned u0 = __float_as_uint(x0), u1 = __float_as_uint(x1);
    unsigned h;
    asm("prmt.b32 %0, %1, %2, 0x7632;" : "=r"(h) : "r"(u0), "r"(u1));
    float l0 = x0 - __uint_as_float(u0 & 0xFFFF0000u);
    float l1 = x1 - __uint_as_float(u1 & 0xFFFF0000u);
    unsigned lp;
    asm("cvt.rn.bf16x2.f32 %0, %1, %2;" : "=r"(lp) : "f"(l1), "f"(l0));
    hi = h; lo = lp;
}

__device__ __forceinline__ void mma_bf16(float* c,
    unsigned a0, unsigned a1, unsigned a2, unsigned a3, unsigned b0, unsigned b1)
{
    asm("mma.sync.aligned.m16n8k16.row.col.f32.bf16.bf16.f32 "
        "{%0,%1,%2,%3}, {%4,%5,%6,%7}, {%8,%9}, {%0,%1,%2,%3};"
        : "+f"(c[0]), "+f"(c[1]), "+f"(c[2]), "+f"(c[3])
        : "r"(a0), "r"(a1), "r"(a2), "r"(a3), "r"(b0), "r"(b1));
}

__device__ __forceinline__ void cp16(void* dst, const void* src)
{
    unsigned d = (unsigned)__cvta_generic_to_shared(dst);
    asm volatile("cp.async.cg.shared.global [%0], [%1], 16;" :: "r"(d), "l"(src));
}
#define CP_COMMIT() asm volatile("cp.async.commit_group;")

__device__ __forceinline__ void fma2_acc(unsigned long long& acc, float a, float b,
                                         unsigned long long one2)
{
    asm("{\n\t.reg .b64 p;\n\tmov.b64 p, {%1,%2};\n\tfma.rn.f32x2 %0, p, %3, %0;\n\t}"
        : "+l"(acc) : "f"(a), "f"(b), "l"(one2));
}
__device__ __forceinline__ void add2_acc(unsigned long long& acc, float a, float b)
{
    asm("{\n\t.reg .b64 p;\n\tmov.b64 p, {%1,%2};\n\tadd.rn.f32x2 %0, %0, p;\n\t}"
        : "+l"(acc) : "f"(a), "f"(b));
}
__device__ __forceinline__ void unpack2(unsigned long long v, float& lo, float& hi)
{
    asm("mov.b64 {%0,%1}, %2;" : "=f"(lo), "=f"(hi) : "l"(v));
}

// ---------------------------------------------------------------------------
// Convert: split 5 f32 matrices into packed hi/lo planes. grid (512,1,5)x256.
// ---------------------------------------------------------------------------
__global__ __launch_bounds__(256) void convert_kernel(
    const float* __restrict__ X, const float* __restrict__ Wq,
    const float* __restrict__ Wk, const float* __restrict__ Wv,
    const float* __restrict__ Wo)
{
    const float* src; unsigned* dh; unsigned* dl;
    switch (blockIdx.z) {
        case 0:  src = X;  dh = g_Xh;  dl = g_Xl;  break;
        case 1:  src = Wq; dh = g_Wqh; dl = g_Wql; break;
        case 2:  src = Wk; dh = g_Wkh; dl = g_Wkl; break;
        case 3:  src = Wv; dh = g_Wvh; dl = g_Wvl; break;
        default: src = Wo; dh = g_Woh; dl = g_Wol; break;
    }
    int idx = blockIdx.x * 256 + threadIdx.x;
    float2 v = *(const float2*)(src + idx * 2);
    unsigned h, l; split2(v.x, v.y, h, l);
    dh[idx] = h; dl[idx] = l;
}

// ---------------------------------------------------------------------------
// GEMM NT on pre-split planes: 32(M) x 32(N) CTA tile, BK=16, 128 threads
// (4 warps 2x2, warp tile 16x16), cp.async 4-stage pipeline, pad-12 rows.
// Dumb loaders: 1 cp16 for A + 1 cp16 for B per thread per kb.
// ---------------------------------------------------------------------------
__device__ __forceinline__ void gemm32(
    const unsigned* __restrict__ Aph, const unsigned* __restrict__ Apl,
    const unsigned* __restrict__ Bph, const unsigned* __restrict__ Bpl,
    const float* __restrict__ bias, float* __restrict__ out,
    unsigned* __restrict__ outh, unsigned* __restrict__ outl)
{
    __shared__ unsigned smA[4][2][32][12];
    __shared__ unsigned smB[4][2][32][12];

    int t = threadIdx.x;
    int row0 = blockIdx.y * 32, col0 = blockIdx.x * 32;
    int lane = t & 31, warp = t >> 5;
    int wm = warp >> 1, wn = warp & 1;
    int g = lane >> 2, tq = lane & 3;

    int p = t >> 6, lr = (t >> 1) & 31, half = t & 1;

    const unsigned* Asrc = (p ? Apl : Aph) + (row0 + lr) * 256 + half * 4;
    const unsigned* Bsrc = (p ? Bpl : Bph) + (col0 + lr) * 256 + half * 4;

    float acc[2][4];
#pragma unroll
    for (int nt = 0; nt < 2; nt++)
#pragma unroll
        for (int x = 0; x < 4; x++) acc[nt][x] = 0.0f;

#pragma unroll
    for (int s = 0; s < 3; s++) {
        cp16(&smA[s][p][lr][half * 4], Asrc + s * 8);
        cp16(&smB[s][p][lr][half * 4], Bsrc + s * 8);
        CP_COMMIT();
    }

#pragma unroll 1
    for (int kb = 0; kb < 32; kb++) {
        asm volatile("cp.async.wait_group 2;");
        __syncthreads();
        if (kb + 3 < 32) {
            int s = (kb + 3) & 3;
            cp16(&smA[s][p][lr][half * 4], Asrc + (kb + 3) * 8);
            cp16(&smB[s][p][lr][half * 4], Bsrc + (kb + 3) * 8);
        }
        CP_COMMIT();

        int st = kb & 3;
        int r = wm * 16 + g;
        unsigned ah0 = smA[st][0][r][tq],     ah1 = smA[st][0][r + 8][tq];
        unsigned ah2 = smA[st][0][r][tq + 4], ah3 = smA[st][0][r + 8][tq + 4];
        unsigned al0 = smA[st][1][r][tq],     al1 = smA[st][1][r + 8][tq];
        unsigned al2 = smA[st][1][r][tq + 4], al3 = smA[st][1][r + 8][tq + 4];
#pragma unroll
        for (int nt = 0; nt < 2; nt++) {
            int n = wn * 16 + nt * 8 + g;
            unsigned bh0 = smB[st][0][n][tq], bh1 = smB[st][0][n][tq + 4];
            unsigned bl0 = smB[st][1][n][tq], bl1 = smB[st][1][n][tq + 4];
            mma_bf16(acc[nt], ah0, ah1, ah2, ah3, bh0, bh1);
            mma_bf16(acc[nt], ah0, ah1, ah2, ah3, bl0, bl1);
            mma_bf16(acc[nt], al0, al1, al2, al3, bh0, bh1);
        }
    }
    asm volatile("cp.async.wait_group 0;");

#pragma unroll
    for (int nt = 0; nt < 2; nt++) {
        int row = row0 + wm * 16 + g;
        int col = col0 + wn * 16 + nt * 8 + 2 * tq;
        float2 b2 = *(const float2*)(bias + col);
        float v0 = acc[nt][0] + b2.x, v1 = acc[nt][1] + b2.y;
        float v2 = acc[nt][2] + b2.x, v3 = acc[nt][3] + b2.y;
        *(float2*)(out + row * HIDDEN + col) = make_float2(v0, v1);
        *(float2*)(out + (row + 8) * HIDDEN + col) = make_float2(v2, v3);
        if (outh) {
            unsigned h, l;
            split2(v0, v1, h, l);
            outh[row * 256 + (col >> 1)] = h; outl[row * 256 + (col >> 1)] = l;
            split2(v2, v3, h, l);
            outh[(row + 8) * 256 + (col >> 1)] = h; outl[(row + 8) * 256 + (col >> 1)] = l;
        }
    }
}

__global__ __launch_bounds__(128) void qkv_mma_kernel(
    const float* __restrict__ bq, const float* __restrict__ bk,
    const float* __restrict__ bv)
{
    if (blockIdx.z == 0)
        gemm32(g_Xh, g_Xl, g_Wqh, g_Wql, bq, g_q, g_qh, g_ql);
    else if (blockIdx.z == 1)
        gemm32(g_Xh, g_Xl, g_Wkh, g_Wkl, bk, g_k, g_kh, g_kl);
    else
        gemm32(g_Xh, g_Xl, g_Wvh, g_Wvl, bv, g_v, (unsigned*)0, (unsigned*)0);
}

__global__ __launch_bounds__(128) void out_mma_kernel(
    const float* __restrict__ bo, float* __restrict__ out)
{
    gemm32(g_Ch, g_Cl, g_Woh, g_Wol, bo, out, (unsigned*)0, (unsigned*)0);
}

// ---------------------------------------------------------------------------
// Norms: zq[h][i] = coef*|q|^2 ; zkm[h][j] = coef*|k|^2 + zc + (1-mask)*1e10
// ---------------------------------------------------------------------------
__global__ __launch_bounds__(128) void norm_kernel(
    const float* __restrict__ mask, const float* __restrict__ gamma)
{
    int id = blockIdx.x * 128 + threadIdx.x;
    int which = id >> 12, head = (id >> 9) & 7, row = id & 511;
    const float* src = (which ? g_k : g_q) + row * HIDDEN + head * HD;
    float s = 0.0f;
#pragma unroll
    for (int c = 0; c < 16; c++) {
        float4 f = *(const float4*)(src + c * 4);
        s = fmaf(f.x, f.x, s); s = fmaf(f.y, f.y, s);
        s = fmaf(f.z, f.z, s); s = fmaf(f.w, f.w, s);
    }
    float gsd = gamma[0] * 8.0f;
    float coef = 15.0f / (16.0f * gsd);
    float zc = 12.0f / gsd;
    if (which)
        g_zkm[head * SEQ + row] = fmaf(coef, s, zc + (1.0f - mask[row]) * 1e10f);
    else
        g_zq[head * SEQ + row] = coef * s;
}

// ---------------------------------------------------------------------------
// FUSED inhibitor: CTA = (i-tile 64, head, j-part 64), 256 threads (8 warps).
// Per 32-j chunk: MMA z-tile (bf16x3) -> affine epilogue -> zst transposed
// smem -> streaming accumulation (4i x 4k per thread, packed f32x2).
// ctx[i,k] = sum_j max(v,z) - sum_j z.  grid (8,8,8) = 512 CTAs.
// ---------------------------------------------------------------------------
__global__ __launch_bounds__(256) void fused_kernel(const float* __restrict__ gamma)
{
    __shared__ unsigned smq[2][64][36];  // q hi/lo planes [row][packed-k]
    __shared__ unsigned smk[2][32][36];  // k chunk planes
    __shared__ float vs[32][68];         // v chunk [j][k]
    __shared__ float zst[32][68];        // z tile TRANSPOSED [j][i]

    int t = threadIdx.x;
    int i0 = blockIdx.x * 64, head = blockIdx.y, jp = blockIdx.z;
    int j0 = jp * 64;

    // stage q planes (cp.async)
    {
        int p = t >> 7, row = (t >> 1) & 63, half = t & 1;
        const unsigned* src = (p ? g_ql : g_qh) + (i0 + row) * 256 + head * 32 + half * 16;
#pragma unroll
        for (int s = 0; s < 4; s++)
            cp16(&smq[p][row][half * 16 + s * 4], src + s * 4);
        CP_COMMIT();
    }

    // prefetch chunk 0: k planes + v (registers)
    int kp = t >> 7, krow = (t >> 2) & 31, kq4 = t & 3;
    const unsigned* kplane = kp ? g_kl : g_kh;
    uint4 kr0, kr1;
    {
        const unsigned* s0 = kplane + (j0 + krow) * 256 + head * 32 + kq4 * 8;
        kr0 = *(const uint4*)(s0); kr1 = *(const uint4*)(s0 + 4);
    }
    int vrow = t >> 3, vseg = t & 7;
    float4 vr0, vr1;
    {
        const float* s0 = g_v + (j0 + vrow) * HIDDEN + head * HD + vseg * 8;
        vr0 = *(const float4*)(s0); vr1 = *(const float4*)(s0 + 4);
    }

    int lane = t & 31, warp = t >> 5;
    int wm = warp >> 1, wn = warp & 1;
    int g = lane >> 2, tq = lane & 3;

    float gsd = gamma[0] * 8.0f;
    float m2c = -2.0f * 15.0f / (16.0f * gsd);
    float zq0 = g_zq[head * SEQ + i0 + wm * 16 + g];
    float zq1 = g_zq[head * SEQ + i0 + wm * 16 + g + 8];

    int ig = t >> 4, kg = t & 15;   // accumulation: 4i x 4k per thread

    const unsigned long long one2 = 0x3F8000003F800000ULL;
    unsigned long long acc2[4][2];
#pragma unroll
    for (int a = 0; a < 4; a++) { acc2[a][0] = 0ULL; acc2[a][1] = 0ULL; }
    unsigned long long accz01 = 0ULL, accz23 = 0ULL;

    asm volatile("cp.async.wait_group 0;");

#pragma unroll 1
    for (int c = 0; c < 2; c++) {
        __syncthreads();   // prev chunk consumers done; q visible (c=0)
        *(uint4*)&smk[kp][krow][kq4 * 8]     = kr0;
        *(uint4*)&smk[kp][krow][kq4 * 8 + 4] = kr1;
        *(float4*)&vs[vrow][vseg * 8]     = vr0;
        *(float4*)&vs[vrow][vseg * 8 + 4] = vr1;
        if (c < 1) {
            const unsigned* s0 = kplane + (j0 + 32 + krow) * 256 + head * 32 + kq4 * 8;
            kr0 = *(const uint4*)(s0); kr1 = *(const uint4*)(s0 + 4);
            const float* sv = g_v + (j0 + 32 + vrow) * HIDDEN + head * HD + vseg * 8;
            vr0 = *(const float4*)(sv); vr1 = *(const float4*)(sv + 4);
        }
        __syncthreads();

        // z = m2c*(q.k) + zq[i] + zkm[j] via mma, into zst (transposed)
        {
            float za[2][4];
#pragma unroll
            for (int nt = 0; nt < 2; nt++)
#pragma unroll
                for (int x = 0; x < 4; x++) za[nt][x] = 0.0f;

            int r = wm * 16 + g;
#pragma unroll
            for (int kb = 0; kb < 4; kb++) {
                int base = kb * 8;
                unsigned ah0 = smq[0][r][base + tq],     ah1 = smq[0][r + 8][base + tq];
                unsigned ah2 = smq[0][r][base + tq + 4], ah3 = smq[0][r + 8][base + tq + 4];
                unsigned al0 = smq[1][r][base + tq],     al1 = smq[1][r + 8][base + tq];
                unsigned al2 = smq[1][r][base + tq + 4], al3 = smq[1][r + 8][base + tq + 4];
#pragma unroll
                for (int nt = 0; nt < 2; nt++) {
                    int n = wn * 16 + nt * 8 + g;
                    unsigned bh0 = smk[0][n][base + tq], bh1 = smk[0][n][base + tq + 4];
                    unsigned bl0 = smk[1][n][base + tq], bl1 = smk[1][n][base + tq + 4];
                    mma_bf16(za[nt], ah0, ah1, ah2, ah3, bh0, bh1);
                    mma_bf16(za[nt], ah0, ah1, ah2, ah3, bl0, bl1);
                    mma_bf16(za[nt], al0, al1, al2, al3, bh0, bh1);
                }
            }
#pragma unroll
            for (int nt = 0; nt < 2; nt++) {
                int col = wn * 16 + nt * 8 + 2 * tq;
                float2 zk = *(const float2*)(g_zkm + head * SEQ + j0 + c * 32 + col);
                zst[col][r]         = fmaf(m2c, za[nt][0], zq0 + zk.x);
                zst[col + 1][r]     = fmaf(m2c, za[nt][1], zq0 + zk.y);
                zst[col][r + 8]     = fmaf(m2c, za[nt][2], zq1 + zk.x);
                zst[col + 1][r + 8] = fmaf(m2c, za[nt][3], zq1 + zk.y);
            }
        }
        __syncthreads();

        // accumulation: acc2 += max(v, z) (packed); accz += z (packed)
#pragma unroll 4
        for (int jj = 0; jj < 32; jj++) {
            float4 z4 = *(const float4*)&zst[jj][ig * 4];
            float4 v4 = *(const float4*)&vs[jj][kg * 4];
            add2_acc(accz01, z4.x, z4.y);
            add2_acc(accz23, z4.z, z4.w);
            float za[4] = {z4.x, z4.y, z4.z, z4.w};
#pragma unroll
            for (int a = 0; a < 4; a++) {
                float z = za[a];
                fma2_acc(acc2[a][0], fmaxf(v4.x, z), fmaxf(v4.y, z), one2);
                fma2_acc(acc2[a][1], fmaxf(v4.z, z), fmaxf(v4.w, z), one2);
            }
        }
    }

    float az[4];
    unpack2(accz01, az[0], az[1]);
    unpack2(accz23, az[2], az[3]);
#pragma unroll
    for (int a = 0; a < 4; a++) {
        float a0, a1, a2, a3;
        unpack2(acc2[a][0], a0, a1);
        unpack2(acc2[a][1], a2, a3);
        float* outp = g_ctx[jp] + (i0 + ig * 4 + a) * HIDDEN + head * HD + kg * 4;
        *(float4*)outp = make_float4(a0 - az[a], a1 - az[a], a2 - az[a], a3 - az[a]);
    }
}

// ---------------------------------------------------------------------------
// Reduce 8 partials and emit packed hi/lo planes of ctxsum. grid 512x256.
// ---------------------------------------------------------------------------
__global__ __launch_bounds__(256) void reduce_kernel()
{
    int idx = blockIdx.x * 256 + threadIdx.x;
    float2 s = make_float2(0.0f, 0.0f);
#pragma unroll
    for (int p = 0; p < NPART; p++) {
        float2 v = *(const float2*)&g_ctx[p][idx * 2];
        s.x += v.x; s.y += v.y;
    }
    unsigned h, l; split2(s.x, s.y, h, l);
    g_Ch[idx] = h; g_Cl[idx] = l;
}

extern "C" void kernel_launch(void* const* d_in, const int* in_sizes, int n_in,
                              void* d_out, int out_size)
{
    const float* X     = (const float*)d_in[0];
    const float* mask  = (const float*)d_in[1];
    const float* Wq    = (const float*)d_in[2];
    const float* bq    = (const float*)d_in[3];
    const float* Wk    = (const float*)d_in[4];
    const float* bk    = (const float*)d_in[5];
    const float* Wv    = (const float*)d_in[6];
    const float* bv    = (const float*)d_in[7];
    const float* Wo    = (const float*)d_in[8];
    const float* bo    = (const float*)d_in[9];
    const float* gamma = (const float*)d_in[10];
    float* out = (float*)d_out;

    convert_kernel<<<dim3(512, 1, 5), 256>>>(X, Wq, Wk, Wv, Wo);
    qkv_mma_kernel<<<dim3(16, 16, 3), 128>>>(bq, bk, bv);
    norm_kernel<<<64, 128>>>(mask, gamma);
    fused_kernel<<<dim3(8, 8, NPART), 256>>>(gamma);
    reduce_kernel<<<512, 256>>>();
    out_mma_kernel<<<dim3(16, 16), 128>>>(bo, out);
}